// round 6
// baseline (speedup 1.0000x reference)
#include <cuda_runtime.h>

#define B_SZ 1024
#define N_SZ 16
#define T_SZ 256

// base index into the packed-pair triangle: row i owns floor(i/2) pairs,
// pair c of row i = (L[i][2c], L[i][2c+1])
__device__ constexpr int pbase(int i) {
    int s = 0;
    for (int r = 0; r < i; r++) s += r / 2;
    return s;
}
#define NPAIRS 56  // pbase(16)

// packed fp32x2 helpers (Blackwell FFMA2 path; only reachable via PTX)
#define FMA2(d_, a_, b_, c_) \
    asm("fma.rn.f32x2 %0, %1, %2, %3;" : "=l"(d_) : "l"(a_), "l"(b_), "l"(c_))
#define PACK2(d_, lo_, hi_) \
    asm("mov.b64 %0, {%1, %2};" : "=l"(d_) : "f"(lo_), "f"(hi_))
#define RED2(out_, acc_) do { float lo_, hi_; \
    asm("mov.b64 {%0, %1}, %2;" : "=f"(lo_), "=f"(hi_) : "l"(acc_)); \
    (out_) = lo_ + hi_; } while (0)

__global__ void gll_zero_kernel(float* out) { out[0] = 0.0f; }

__global__ void __launch_bounds__(T_SZ, 2)
gll_kernel(const float* __restrict__ pred,
           const float* __restrict__ targ,
           const float* __restrict__ cov,
           float* __restrict__ out) {
    const unsigned b = blockIdx.x;   // 0..1023
    const unsigned t = threadIdx.x;  // 0..255
    const unsigned cov_base = b * (N_SZ * N_SZ * T_SZ) + t;

    unsigned long long Lp[NPAIRS];   // strict-lower triangle, packed in k-pairs
    float inv[N_SZ];                 // 1/L_jj
    float lodd[N_SZ / 2];            // L[i][i-1] for odd i (never gets a pair partner)
    float colp[N_SZ];                // previous (even) column's L values
    float pivprod = 1.0f;

    // ---- column-streaming Cholesky: load column j (coalesced over t), factor it.
#pragma unroll
    for (int j = 0; j < N_SZ; j++) {
        float col[N_SZ];
#pragma unroll
        for (int i = j; i < N_SZ; i++)
            col[i] = cov[cov_base + (unsigned)((i * N_SZ + j) * T_SZ)];

        // pivot: s = a_jj - sum_{k<j} L_jk^2
        float s = col[j];
        if (j >= 2) {
            unsigned long long acc = 0ull;
#pragma unroll
            for (int c = 0; c < j / 2; c++)
                FMA2(acc, Lp[pbase(j) + c], Lp[pbase(j) + c], acc);
            float r; RED2(r, acc);
            s -= r;
        }
        if (j & 1) s -= colp[j] * colp[j];      // scalar tail k = j-1
        pivprod *= s;                            // pivots >= 1 (Sigma = AA^T + I)
        const float iv = rsqrtf(s);
        inv[j] = iv;

        // off-diagonals of column j
#pragma unroll
        for (int i = j + 1; i < N_SZ; i++) {
            float s2 = col[i];
            if (j >= 2) {
                unsigned long long acc = 0ull;
#pragma unroll
                for (int c = 0; c < j / 2; c++)
                    FMA2(acc, Lp[pbase(i) + c], Lp[pbase(j) + c], acc);
                float r; RED2(r, acc);
                s2 -= r;
            }
            if (j & 1) s2 -= colp[i] * colp[j];
            col[i] = s2 * iv;
        }

        if (j & 1) {
            // complete pairs (j-1, j) for all remaining rows
#pragma unroll
            for (int i = j + 1; i < N_SZ; i++)
                PACK2(Lp[pbase(i) + j / 2], colp[i], col[i]);
        } else {
            // stash L[j+1][j] (will never be paired when j+1 is odd)
            if (j + 1 < N_SZ) lodd[j / 2] = col[j + 1];
            // buffer this even column for next column's tail + packing
#pragma unroll
            for (int i = j + 1; i < N_SZ; i++)
                colp[i] = col[i];
        }
    }
    const float logdet = __logf(pivprod);

    // ---- diff = pred - target, loaded after factorization (coalesced)
    float d[N_SZ];
    const unsigned pt_base = b * (N_SZ * T_SZ) + t;
#pragma unroll
    for (int i = 0; i < N_SZ; i++) {
        const unsigned off = pt_base + (unsigned)(i * T_SZ);
        d[i] = pred[off] - targ[off];
    }

    // ---- forward solve L y = diff with packed pairs; quad = ||y||^2
    float quad = 0.0f;
    float y_prev = 0.0f;
    unsigned long long yp[N_SZ / 2];  // (y[2c], y[2c+1])
#pragma unroll
    for (int i = 0; i < N_SZ; i++) {
        float s = d[i];
        if (i >= 2) {
            unsigned long long acc = 0ull;
#pragma unroll
            for (int c = 0; c < i / 2; c++)
                FMA2(acc, Lp[pbase(i) + c], yp[c], acc);
            float r; RED2(r, acc);
            s -= r;
        }
        if (i & 1) s -= lodd[i / 2] * y_prev;   // k = i-1 scalar tail
        const float yi = s * inv[i];
        quad += yi * yi;
        if (i & 1) PACK2(yp[i / 2], y_prev, yi);
        y_prev = yi;
    }

    float val = (quad + logdet) * (1.0f / ((float)B_SZ * (float)T_SZ));

    // ---- block reduction: warp shuffle, then smem across 8 warps
#pragma unroll
    for (int off = 16; off > 0; off >>= 1)
        val += __shfl_xor_sync(0xFFFFFFFFu, val, off);

    __shared__ float warp_sums[T_SZ / 32];
    const int lane = threadIdx.x & 31;
    const int wid  = threadIdx.x >> 5;
    if (lane == 0) warp_sums[wid] = val;
    __syncthreads();

    if (wid == 0) {
        float v = (lane < T_SZ / 32) ? warp_sums[lane] : 0.0f;
#pragma unroll
        for (int off = 4; off > 0; off >>= 1)
            v += __shfl_xor_sync(0xFFFFFFFFu, v, off);
        if (lane == 0) atomicAdd(out, v);
    }
}

extern "C" void kernel_launch(void* const* d_in, const int* in_sizes, int n_in,
                              void* d_out, int out_size) {
    const float* pred = (const float*)d_in[0];
    const float* targ = (const float*)d_in[1];
    const float* cov  = (const float*)d_in[2];
    float* out = (float*)d_out;

    gll_zero_kernel<<<1, 1>>>(out);
    gll_kernel<<<B_SZ, T_SZ>>>(pred, targ, cov, out);
}

// round 9
// speedup vs baseline: 28.1341x; 28.1341x over previous
#include <cuda_runtime.h>

#define B_SZ 1024
#define N_SZ 16
#define T_SZ 256
// packed lower-triangular index (compile-time after unroll)
#define TRI(i, j) ((i) * ((i) + 1) / 2 + (j))

// Compiler memory barrier: pins LDG placement per pipeline stage (registers
// are not affected, so FMA scheduling stays free; no SASS instruction emitted).
#define MEM_STAGE() asm volatile("" ::: "memory")

__global__ void __launch_bounds__(T_SZ, 2)
gll_kernel(const float* __restrict__ pred,
           const float* __restrict__ targ,
           const float* __restrict__ cov,
           float* __restrict__ out) {
    const unsigned b = blockIdx.x;   // 0..1023
    const unsigned t = threadIdx.x;  // 0..255

    // 32-bit indexing: max offset = 1024*16*16*256 = 67M, fits in uint32.
    const unsigned cov_base = b * (N_SZ * N_SZ * T_SZ) + t;

    float a[N_SZ * (N_SZ + 1) / 2];

    // ---- software-pipelined column-streaming Cholesky ----
    // Prologue: columns 0 and 1 in flight (coalesced over t; T innermost).
#pragma unroll
    for (int i = 0; i < N_SZ; i++)
        a[TRI(i, 0)] = cov[cov_base + (unsigned)((i * N_SZ + 0) * T_SZ)];
#pragma unroll
    for (int i = 1; i < N_SZ; i++)
        a[TRI(i, 1)] = cov[cov_base + (unsigned)((i * N_SZ + 1) * T_SZ)];
    MEM_STAGE();

    float pivprod = 1.0f;
#pragma unroll
    for (int j = 0; j < N_SZ; j++) {
        // Prefetch column j+2 into its final triangle slots (2-column lookahead).
        if (j + 2 < N_SZ) {
#pragma unroll
            for (int i = j + 2; i < N_SZ; i++)
                a[TRI(i, j + 2)] = cov[cov_base + (unsigned)((i * N_SZ + (j + 2)) * T_SZ)];
        }

        // Compute column j. Pivot: s = a_jj - sum_{k<j} L_jk^2.
        float s = a[TRI(j, j)];
#pragma unroll
        for (int k = 0; k < j; k++) {
            const float l = a[TRI(j, k)];
            s -= l * l;
        }
        // pivots >= 1 (Sigma = A A^T + I): product stays in [1, ~1e26], fp32-safe.
        pivprod *= s;
        const float inv = rsqrtf(s);
        a[TRI(j, j)] = inv;  // diagonal stores 1/L_jj

#pragma unroll
        for (int i = j + 1; i < N_SZ; i++) {
            float s2 = a[TRI(i, j)];
#pragma unroll
            for (int k = 0; k < j; k++) {
                s2 -= a[TRI(i, k)] * a[TRI(j, k)];
            }
            a[TRI(i, j)] = s2 * inv;
        }
        MEM_STAGE();  // pin this stage's loads; next stage's LDGs cannot hoist above
    }
    const float logdet = __logf(pivprod);

    // ---- diff = pred - target (coalesced), after factorization: small live range
    float d[N_SZ];
    const unsigned pt_base = b * (N_SZ * T_SZ) + t;
#pragma unroll
    for (int i = 0; i < N_SZ; i++) {
        const unsigned off = pt_base + (unsigned)(i * T_SZ);
        d[i] = pred[off] - targ[off];
    }

    // ---- forward solve L y = diff; quad = ||y||^2 (diagonal holds 1/L_ii)
    float quad = 0.0f;
    float y[N_SZ];
#pragma unroll
    for (int i = 0; i < N_SZ; i++) {
        float s = d[i];
#pragma unroll
        for (int k = 0; k < i; k++) {
            s -= a[TRI(i, k)] * y[k];
        }
        y[i] = s * a[TRI(i, i)];
        quad += y[i] * y[i];
    }

    float val = (quad + logdet) * (1.0f / ((float)B_SZ * (float)T_SZ));

    // ---- block reduction: warp shuffle, then smem across 8 warps
#pragma unroll
    for (int off = 16; off > 0; off >>= 1)
        val += __shfl_xor_sync(0xFFFFFFFFu, val, off);

    __shared__ float warp_sums[T_SZ / 32];
    const int lane = threadIdx.x & 31;
    const int wid  = threadIdx.x >> 5;
    if (lane == 0) warp_sums[wid] = val;
    __syncthreads();

    if (wid == 0) {
        float v = (lane < T_SZ / 32) ? warp_sums[lane] : 0.0f;
#pragma unroll
        for (int off = 4; off > 0; off >>= 1)
            v += __shfl_xor_sync(0xFFFFFFFFu, v, off);
        if (lane == 0) atomicAdd(out, v);
    }
}

extern "C" void kernel_launch(void* const* d_in, const int* in_sizes, int n_in,
                              void* d_out, int out_size) {
    const float* pred = (const float*)d_in[0];
    const float* targ = (const float*)d_in[1];
    const float* cov  = (const float*)d_in[2];
    float* out = (float*)d_out;

    // Graph-capturable memset node (cheaper than a 1-thread zero kernel).
    cudaMemsetAsync(out, 0, sizeof(float));
    gll_kernel<<<B_SZ, T_SZ>>>(pred, targ, cov, out);
}